// round 7
// baseline (speedup 1.0000x reference)
#include <cuda_runtime.h>
#include <math.h>

// Problem dims
#define Bc   128
#define Nch  128
#define Tc   336
#define Hc   64
#define Kc   4
#define Fc   720
#define BNT  (Bc*Nch)          // 16384

// ---------------- scratch (device globals; no allocs allowed) ----------------
__device__ float g_H1[BNT*128];        // mu|sg hidden, relu'd   (8 MB)
__device__ float g_Hw[BNT*Kc*64];      // wg hidden, relu'd      (16 MB)
__device__ float g_Hf[BNT*Fc];         // fitter hidden, relu'd  (45 MB, reused per fitter)
__device__ float g_spmu[BNT*Kc];
__device__ float g_spsg[BNT*Kc];
__device__ float g_w[BNT*Kc];
__device__ float g_coef[BNT*8];        // 7 coeffs, stride 8
__device__ float g_S[64 + 4*Fc];       // rowsums: wg_W1 then f0..f3 W1

__device__ __forceinline__ float softplus_f(float x) {
    return fmaxf(x, 0.f) + log1pf(expf(-fabsf(x)));
}

// ---------------- rowsum: S[r] = sum_t W[r,t] ----------------
__global__ void rowsum_kernel(const float* __restrict__ W, float* __restrict__ S, int rows) {
    int warp = (blockIdx.x * blockDim.x + threadIdx.x) >> 5;
    int lane = threadIdx.x & 31;
    if (warp >= rows) return;
    const float* row = W + (long)warp * Tc;
    float s = 0.f;
    for (int j = lane; j < Tc; j += 32) s += row[j];
    #pragma unroll
    for (int o = 16; o; o >>= 1) s += __shfl_xor_sync(0xffffffffu, s, o);
    if (lane == 0) S[warp] = s;
}

// ---------------- tiled SGEMM: C[m,n] = epilogue( A[m,:] . W[n,:] ) ----------------
// A row-major [M, Tc] with row stride lda. W row-major [Ncols, Tc].
// MODE 0: C = relu(acc + b1[n])
// MODE 1: C = relu(b1[n] + spmu[idx]*S[n] + spsg[idx]*acc), idx = m*sp_mul + sp_add
#define BM 128
#define BN 64
#define BK 8

template<int MODE>
__global__ __launch_bounds__(256)
void gemm_kernel(const float* __restrict__ A, int lda,
                 const float* __restrict__ W, int Ncols,
                 float* __restrict__ C, int ldc,
                 const float* __restrict__ b1,
                 const float* __restrict__ S,
                 const float* __restrict__ spmu,
                 const float* __restrict__ spsg,
                 int sp_mul, int sp_add)
{
    __shared__ __align__(16) float As[BK][BM + 4];
    __shared__ __align__(16) float Ws[BK][BN + 4];

    const int t  = threadIdx.x;
    const int tx = t & 15;        // 16 col-groups of 4
    const int ty = t >> 4;        // 16 row-groups of 8
    const int m0 = blockIdx.y * BM;
    const int n0 = blockIdx.x * BN;

    float acc[8][4];
    #pragma unroll
    for (int i = 0; i < 8; i++)
        #pragma unroll
        for (int j = 0; j < 4; j++) acc[i][j] = 0.f;

    const int a_m = t >> 1, a_k = (t & 1) * 4;
    const bool w_act = (t < 128);
    const int w_n = t >> 1, w_k = a_k;
    const float* Aptr = A + (long)(m0 + a_m) * lda + a_k;
    const bool w_valid = w_act && (n0 + w_n < Ncols);
    const float* Wptr = W + (long)(n0 + w_n) * Tc + w_k;

    for (int k0 = 0; k0 < Tc; k0 += BK) {
        float4 av = *(const float4*)(Aptr + k0);
        float4 wv = make_float4(0.f, 0.f, 0.f, 0.f);
        if (w_valid) wv = *(const float4*)(Wptr + k0);

        __syncthreads();
        As[a_k + 0][a_m] = av.x; As[a_k + 1][a_m] = av.y;
        As[a_k + 2][a_m] = av.z; As[a_k + 3][a_m] = av.w;
        if (w_act) {
            Ws[w_k + 0][w_n] = wv.x; Ws[w_k + 1][w_n] = wv.y;
            Ws[w_k + 2][w_n] = wv.z; Ws[w_k + 3][w_n] = wv.w;
        }
        __syncthreads();

        #pragma unroll
        for (int kk = 0; kk < BK; kk++) {
            float4 bv = *(const float4*)&Ws[kk][tx * 4];
            float4 a0 = *(const float4*)&As[kk][ty * 8];
            float4 a1 = *(const float4*)&As[kk][ty * 8 + 4];
            float ar[8] = {a0.x, a0.y, a0.z, a0.w, a1.x, a1.y, a1.z, a1.w};
            float br[4] = {bv.x, bv.y, bv.z, bv.w};
            #pragma unroll
            for (int i = 0; i < 8; i++)
                #pragma unroll
                for (int j = 0; j < 4; j++)
                    acc[i][j] += ar[i] * br[j];
        }
    }

    #pragma unroll
    for (int i = 0; i < 8; i++) {
        const int m = m0 + ty * 8 + i;
        float smu = 0.f, ssg = 0.f;
        if (MODE == 1) {
            int idx = m * sp_mul + sp_add;
            smu = spmu[idx]; ssg = spsg[idx];
        }
        #pragma unroll
        for (int j = 0; j < 4; j++) {
            const int n = n0 + tx * 4 + j;
            if (n < Ncols) {
                float v;
                if (MODE == 0) v = acc[i][j] + __ldg(&b1[n]);
                else           v = __ldg(&b1[n]) + smu * __ldg(&S[n]) + ssg * acc[i][j];
                C[(long)m * ldc + n] = fmaxf(v, 0.f);
            }
        }
    }
}

// ---------------- mu/sigma second layer + softplus ----------------
__global__ void musig2_kernel(const float* __restrict__ muW2, const float* __restrict__ mub2,
                              const float* __restrict__ sgW2, const float* __restrict__ sgb2)
{
    int row  = blockIdx.x * 8 + (threadIdx.x >> 5);
    int lane = threadIdx.x & 31;
    if (row >= BNT) return;
    const float* h = g_H1 + (long)row * 128;
    float hm0 = h[lane], hm1 = h[32 + lane];
    float hs0 = h[64 + lane], hs1 = h[96 + lane];
    #pragma unroll
    for (int o = 0; o < 4; o++) {
        float vm = hm0 * muW2[o * 64 + lane] + hm1 * muW2[o * 64 + 32 + lane];
        float vs = hs0 * sgW2[o * 64 + lane] + hs1 * sgW2[o * 64 + 32 + lane];
        #pragma unroll
        for (int s = 16; s; s >>= 1) {
            vm += __shfl_xor_sync(0xffffffffu, vm, s);
            vs += __shfl_xor_sync(0xffffffffu, vs, s);
        }
        if (lane == 0) {
            g_spmu[row * 4 + o] = softplus_f(vm + mub2[o]);
            g_spsg[row * 4 + o] = softplus_f(vs + sgb2[o]);
        }
    }
}

// ---------------- wg second layer + softmax over K ----------------
__global__ void wglogit_kernel(const float* __restrict__ W2, const float* __restrict__ b2)
{
    int bn   = blockIdx.x * 8 + (threadIdx.x >> 5);
    int lane = threadIdx.x & 31;
    if (bn >= BNT) return;
    float lg[4];
    #pragma unroll
    for (int k = 0; k < 4; k++) {
        const float* h = g_Hw + (long)(bn * 4 + k) * 64;
        float v = h[lane] * W2[lane] + h[32 + lane] * W2[32 + lane];
        #pragma unroll
        for (int s = 16; s; s >>= 1) v += __shfl_xor_sync(0xffffffffu, v, s);
        lg[k] = v + b2[0];
    }
    float m = fmaxf(fmaxf(lg[0], lg[1]), fmaxf(lg[2], lg[3]));
    float e0 = expf(lg[0] - m), e1 = expf(lg[1] - m), e2 = expf(lg[2] - m), e3 = expf(lg[3] - m);
    float inv = 1.f / (e0 + e1 + e2 + e3);
    if (lane == 0) {
        g_w[bn * 4 + 0] = e0 * inv; g_w[bn * 4 + 1] = e1 * inv;
        g_w[bn * 4 + 2] = e2 * inv; g_w[bn * 4 + 3] = e3 * inv;
    }
}

// ---------------- fitter second layer: coeffs ----------------
__global__ void coeffs_kernel(const float* __restrict__ W2, const float* __restrict__ b2,
                              int deg, int off)
{
    int bn   = blockIdx.x * 8 + (threadIdx.x >> 5);
    int lane = threadIdx.x & 31;
    if (bn >= BNT) return;
    const float* h = g_Hf + (long)bn * Fc;
    for (int d = 0; d < deg; d++) {
        const float* w2 = W2 + (long)d * Fc;
        float s = 0.f;
        for (int f = lane; f < Fc; f += 32) s += h[f] * w2[f];
        #pragma unroll
        for (int o = 16; o; o >>= 1) s += __shfl_xor_sync(0xffffffffu, s, o);
        if (lane == 0) g_coef[bn * 8 + off + d] = s + b2[d];
    }
}

// ---------------- final: polynomial eval + mixture + transpose ----------------
#define FCHUNK 48
__global__ void final_kernel(float* __restrict__ out)
{
    int b  = blockIdx.y;
    int f0 = blockIdx.x * FCHUNK;
    int n  = threadIdx.x;
    int bn = b * Nch + n;
    float w0 = g_w[bn * 4 + 0], w1 = g_w[bn * 4 + 1], w2 = g_w[bn * 4 + 2], w3 = g_w[bn * 4 + 3];
    float c0 = g_coef[bn * 8 + 0];
    float c1 = g_coef[bn * 8 + 1], c2 = g_coef[bn * 8 + 2];
    float c3 = g_coef[bn * 8 + 3], c4 = g_coef[bn * 8 + 4], c5 = g_coef[bn * 8 + 5];
    float c6 = g_coef[bn * 8 + 6];
    #pragma unroll 4
    for (int fi = 0; fi < FCHUNK; fi++) {
        int f = f0 + fi;
        float tt = (float)f * (1.f / 719.f);
        float t2 = tt * tt, t3 = t2 * tt;
        float p0 = c0 + 0.5f * tt;
        float p1 = c1 + c2 * tt + 0.5f * t2;
        float p2 = c3 + c4 * tt + c5 * t2 + 0.5f * t3;
        float p3 = c6 - 0.5f * tt;
        out[((long)b * Fc + f) * Nch + n] = w0 * p0 + w1 * p1 + w2 * p2 + w3 * p3;
    }
}

// ---------------- launch ----------------
extern "C" void kernel_launch(void* const* d_in, const int* in_sizes, int n_in,
                              void* d_out, int out_size)
{
    const float* x     = (const float*)d_in[0];
    const float* eps   = (const float*)d_in[1];
    const float* muW1  = (const float*)d_in[2];
    const float* mub1  = (const float*)d_in[3];
    const float* muW2  = (const float*)d_in[4];
    const float* mub2  = (const float*)d_in[5];
    const float* sgW1  = (const float*)d_in[6];
    const float* sgb1  = (const float*)d_in[7];
    const float* sgW2  = (const float*)d_in[8];
    const float* sgb2  = (const float*)d_in[9];
    const float* wgW1  = (const float*)d_in[10];
    const float* wgb1  = (const float*)d_in[11];
    const float* wgW2  = (const float*)d_in[12];
    const float* wgb2  = (const float*)d_in[13];
    const float* fW1[4] = {(const float*)d_in[14], (const float*)d_in[18],
                           (const float*)d_in[22], (const float*)d_in[26]};
    const float* fb1[4] = {(const float*)d_in[15], (const float*)d_in[19],
                           (const float*)d_in[23], (const float*)d_in[27]};
    const float* fW2[4] = {(const float*)d_in[16], (const float*)d_in[20],
                           (const float*)d_in[24], (const float*)d_in[28]};
    const float* fb2[4] = {(const float*)d_in[17], (const float*)d_in[21],
                           (const float*)d_in[25], (const float*)d_in[29]};
    float* out = (float*)d_out;

    float* H1;  cudaGetSymbolAddress((void**)&H1,  g_H1);
    float* Hw;  cudaGetSymbolAddress((void**)&Hw,  g_Hw);
    float* Hf;  cudaGetSymbolAddress((void**)&Hf,  g_Hf);
    float* spm; cudaGetSymbolAddress((void**)&spm, g_spmu);
    float* sps; cudaGetSymbolAddress((void**)&sps, g_spsg);
    float* Sp;  cudaGetSymbolAddress((void**)&Sp,  g_S);

    // rowsums (wg + 4 fitters)
    rowsum_kernel<<<(64 * 32 + 255) / 256, 256>>>(wgW1, Sp, 64);
    for (int i = 0; i < 4; i++)
        rowsum_kernel<<<(Fc * 32 + 255) / 256, 256>>>(fW1[i], Sp + 64 + i * Fc, Fc);

    // mu / sigma hidden: x @ [muW1;sgW1]^T -> g_H1 [16384,128]
    {
        dim3 grid(1, BNT / BM);
        gemm_kernel<0><<<grid, 256>>>(x, Tc, muW1, Hc, H1,      128, mub1, nullptr, nullptr, nullptr, 0, 0);
        gemm_kernel<0><<<grid, 256>>>(x, Tc, sgW1, Hc, H1 + 64, 128, sgb1, nullptr, nullptr, nullptr, 0, 0);
    }
    musig2_kernel<<<BNT / 8, 256>>>(muW2, mub2, sgW2, sgb2);

    // wg hidden: eps [65536,336] -> g_Hw [65536,64]
    {
        dim3 grid(1, (BNT * Kc) / BM);
        gemm_kernel<1><<<grid, 256>>>(eps, Tc, wgW1, Hc, Hw, 64, wgb1, Sp, spm, sps, 1, 0);
    }
    wglogit_kernel<<<BNT / 8, 256>>>(wgW2, wgb2);

    // fitters
    static const int DEG[4] = {1, 2, 3, 1};
    static const int OFF[4] = {0, 1, 3, 6};
    for (int i = 0; i < 4; i++) {
        dim3 grid((Fc + BN - 1) / BN, BNT / BM);
        gemm_kernel<1><<<grid, 256>>>(eps + i * Tc, Kc * Tc, fW1[i], Fc, Hf, Fc,
                                      fb1[i], Sp + 64 + i * Fc, spm, sps, 4, i);
        coeffs_kernel<<<BNT / 8, 256>>>(fW2[i], fb2[i], DEG[i], OFF[i]);
    }

    // final mixture + transpose
    {
        dim3 grid(Fc / FCHUNK, Bc);
        final_kernel<<<grid, 128>>>(out);
    }
}

// round 9
// speedup vs baseline: 2.0044x; 2.0044x over previous
#include <cuda_runtime.h>
#include <cuda_bf16.h>
#include <math.h>
#include <stdint.h>

#define Tc   336
#define BNT  16384
#define Fc   720
#define Nch  128
#define Bc   128
#define KC   48          // k-cols per smem stage
#define NSTG 7           // 336/48
#define NT   64          // n-tile per pass
#define RSTR 112         // smem tile row stride bytes (56 bf16; 112/16=7 coprime 8)

// smem layout (bytes)
#define SM_A_HI 0
#define SM_A_LO 14336
#define SM_B_HI 28672
#define SM_B_LO 35840
#define SM_STG  43008    // 6*64 floats
#define SM_RED  44544    // 128*4 floats
#define SM_TOT  46592

// ---------------- scratch globals ----------------
__device__ float g_ms[BNT*8];
__device__ float g_spmu[BNT*4];
__device__ float g_spsg[BNT*4];
__device__ float g_lg[BNT*4];
__device__ float g_w[BNT*4];
__device__ float g_coef[BNT*8];
__device__ float g_S[64 + 4*Fc];

__device__ __forceinline__ float softplus_f(float x){
    return fmaxf(x,0.f) + log1pf(expf(-fabsf(x)));
}
__device__ __forceinline__ uint32_t su32(const void* p){
    uint32_t a;
    asm("{ .reg .u64 t; cvta.to.shared.u64 t, %1; cvt.u32.u64 %0, t; }" : "=r"(a) : "l"(p));
    return a;
}

#define LDSM4(r, a) asm volatile( \
    "ldmatrix.sync.aligned.m8n8.x4.shared.b16 {%0,%1,%2,%3}, [%4];" \
    : "=r"((r)[0]), "=r"((r)[1]), "=r"((r)[2]), "=r"((r)[3]) : "r"(a))
#define LDSM2(r, a) asm volatile( \
    "ldmatrix.sync.aligned.m8n8.x2.shared.b16 {%0,%1}, [%2];" \
    : "=r"((r)[0]), "=r"((r)[1]) : "r"(a))
#define MMA(c, a, b) asm volatile( \
    "mma.sync.aligned.m16n8k16.row.col.f32.bf16.bf16.f32 " \
    "{%0,%1,%2,%3}, {%4,%5,%6,%7}, {%8,%9}, {%0,%1,%2,%3};" \
    : "+f"((c)[0]), "+f"((c)[1]), "+f"((c)[2]), "+f"((c)[3]) \
    : "r"((a)[0]), "r"((a)[1]), "r"((a)[2]), "r"((a)[3]), "r"((b)[0]), "r"((b)[1]))

__device__ __forceinline__ void cvt_split(float4 v, uint2& h, uint2& lo){
    __nv_bfloat162 h01 = __floats2bfloat162_rn(v.x, v.y);
    __nv_bfloat162 h23 = __floats2bfloat162_rn(v.z, v.w);
    float2 f01 = __bfloat1622float2(h01), f23 = __bfloat1622float2(h23);
    __nv_bfloat162 l01 = __floats2bfloat162_rn(v.x - f01.x, v.y - f01.y);
    __nv_bfloat162 l23 = __floats2bfloat162_rn(v.z - f23.x, v.w - f23.y);
    h  = make_uint2(*(uint32_t*)&h01, *(uint32_t*)&h23);
    lo = make_uint2(*(uint32_t*)&l01, *(uint32_t*)&l23);
}

// =====================================================================
// Fused split-bf16 mma.sync GEMM + reduce epilogue.
//   acc[m,n] = A[m,:].W1[n,:]  (K=336)
//   h = relu(b1[n] + smu[m]*S[n] + ssg[m]*acc)
//   out[m*ostride+ooff+d] = sum_n h*W2[d,n]
// =====================================================================
__device__ __forceinline__ void gemm_core(
    const float* __restrict__ A, int lda,
    const float* __restrict__ W1, int Ncols, int n_nt,
    const float* __restrict__ b1, const float* __restrict__ S,
    const float* __restrict__ spmu, const float* __restrict__ spsg,
    int sp_mul, int sp_add,
    const float* __restrict__ W2, int R,
    float* __restrict__ outp, int ostride, int ooff)
{
    __shared__ __align__(16) char smem[SM_TOT];
    const int tid = threadIdx.x;
    const int wid = tid >> 5, lane = tid & 31;
    const int g = lane >> 2, l = lane & 3;
    const int wm = wid >> 2, wn = wid & 3;
    const int m0 = blockIdx.x * 128;

    const uint32_t sb = su32(smem);
    float* stg = (float*)(smem + SM_STG);
    float* red = (float*)(smem + SM_RED);

    if (tid < 128) ((float4*)red)[tid] = make_float4(0.f,0.f,0.f,0.f);

    float smu8[8], ssg8[8];
    #pragma unroll
    for (int s = 0; s < 8; s++) {
        if (spmu != nullptr) {
            int row = m0 + wm*64 + (s>>1)*16 + g + (s&1)*8;
            smu8[s] = spmu[row*sp_mul + sp_add];
            ssg8[s] = spsg[row*sp_mul + sp_add];
        } else { smu8[s] = 0.f; ssg8[s] = 1.f; }
    }

    float part[8][4];
    #pragma unroll
    for (int s = 0; s < 8; s++)
        #pragma unroll
        for (int d = 0; d < 4; d++) part[s][d] = 0.f;

    for (int nt = 0; nt < n_nt; nt++) {
        __syncthreads();
        // staging: b1 / S / W2 rows for this n-tile
        for (int idx = tid; idx < 64*(2+R); idx += 256) {
            int n = idx & 63, row = idx >> 6;
            int gn = nt*NT + n;
            float v = 0.f;
            if (gn < Ncols) {
                if (row == 0)      v = b1[gn];
                else if (row == 1) v = (S != nullptr) ? S[gn] : 0.f;
                else               v = W2[(row-2)*Ncols + gn];
            }
            stg[row*64 + n] = v;
        }

        float acc[4][2][4];
        #pragma unroll
        for (int i = 0; i < 4; i++)
            #pragma unroll
            for (int j = 0; j < 2; j++)
                #pragma unroll
                for (int e = 0; e < 4; e++) acc[i][j][e] = 0.f;

        float4 pa[6], pb[3];
        // prefetch stage 0
        #pragma unroll
        for (int it = 0; it < 6; it++) {
            int q = tid + it*256; int r = q/12, cq = q - r*12;
            pa[it] = *(const float4*)(A + (long)(m0 + r)*lda + cq*4);
        }
        #pragma unroll
        for (int it = 0; it < 3; it++) {
            int q = tid + it*256; int n = q/12, cq = q - n*12;
            int gn = nt*NT + n;
            pb[it] = (gn < Ncols) ? *(const float4*)(W1 + (long)gn*Tc + cq*4)
                                  : make_float4(0.f,0.f,0.f,0.f);
        }

        for (int kc = 0; kc < NSTG; kc++) {
            __syncthreads();
            // store current stage (convert fp32 -> hi/lo bf16)
            #pragma unroll
            for (int it = 0; it < 6; it++) {
                int q = tid + it*256; int r = q/12, cq = q - r*12;
                uint2 h, lo; cvt_split(pa[it], h, lo);
                *(uint2*)(smem + SM_A_HI + r*RSTR + cq*8) = h;
                *(uint2*)(smem + SM_A_LO + r*RSTR + cq*8) = lo;
            }
            #pragma unroll
            for (int it = 0; it < 3; it++) {
                int q = tid + it*256; int n = q/12, cq = q - n*12;
                uint2 h, lo; cvt_split(pb[it], h, lo);
                *(uint2*)(smem + SM_B_HI + n*RSTR + cq*8) = h;
                *(uint2*)(smem + SM_B_LO + n*RSTR + cq*8) = lo;
            }
            __syncthreads();
            // prefetch next stage
            if (kc + 1 < NSTG) {
                int kb = (kc+1)*KC;
                #pragma unroll
                for (int it = 0; it < 6; it++) {
                    int q = tid + it*256; int r = q/12, cq = q - r*12;
                    pa[it] = *(const float4*)(A + (long)(m0 + r)*lda + kb + cq*4);
                }
                #pragma unroll
                for (int it = 0; it < 3; it++) {
                    int q = tid + it*256; int n = q/12, cq = q - n*12;
                    int gn = nt*NT + n;
                    pb[it] = (gn < Ncols) ? *(const float4*)(W1 + (long)gn*Tc + kb + cq*4)
                                          : make_float4(0.f,0.f,0.f,0.f);
                }
            }
            // MMA over 3 k16 steps
            #pragma unroll
            for (int ks = 0; ks < 3; ks++) {
                uint32_t ah[4][4], al[4][4];
                #pragma unroll
                for (int i = 0; i < 4; i++) {
                    int row = wm*64 + i*16 + (lane & 15);
                    uint32_t ad = sb + SM_A_HI + row*RSTR + ks*32 + ((lane>>4)<<4);
                    LDSM4(ah[i], ad);
                    LDSM4(al[i], ad + (SM_A_LO - SM_A_HI));
                }
                uint32_t bh[2][2], bl[2][2];
                #pragma unroll
                for (int j = 0; j < 2; j++) {
                    int rowb = wn*16 + j*8 + (lane & 7);
                    uint32_t ad = sb + SM_B_HI + rowb*RSTR + ks*32 + (((lane>>3)&1)<<4);
                    LDSM2(bh[j], ad);
                    LDSM2(bl[j], ad + (SM_B_LO - SM_B_HI));
                }
                #pragma unroll
                for (int i = 0; i < 4; i++)
                    #pragma unroll
                    for (int j = 0; j < 2; j++) {
                        MMA(acc[i][j], ah[i], bh[j]);
                        MMA(acc[i][j], ah[i], bl[j]);
                        MMA(acc[i][j], al[i], bh[j]);
                    }
            }
        }
        // epilogue: relu + affine + partial reduction over n
        #pragma unroll
        for (int i = 0; i < 4; i++)
            #pragma unroll
            for (int j = 0; j < 2; j++)
                #pragma unroll
                for (int e = 0; e < 4; e++) {
                    int nl = wn*16 + j*8 + 2*l + (e&1);
                    int s  = i*2 + (e>>1);
                    float hv = fmaxf(stg[nl] + smu8[s]*stg[64+nl] + ssg8[s]*acc[i][j][e], 0.f);
                    #pragma unroll
                    for (int d = 0; d < 4; d++)
                        if (d < R) part[s][d] += stg[(2+d)*64 + nl] * hv;
                }
    }

    // cross-lane reduce (lanes sharing g) then cross-warp via smem atomics
    #pragma unroll
    for (int s = 0; s < 8; s++)
        #pragma unroll
        for (int d = 0; d < 4; d++) {
            float v = part[s][d];
            v += __shfl_xor_sync(0xffffffffu, v, 1);
            v += __shfl_xor_sync(0xffffffffu, v, 2);
            part[s][d] = v;
        }
    __syncthreads();
    if (l == 0) {
        #pragma unroll
        for (int s = 0; s < 8; s++) {
            int row = wm*64 + (s>>1)*16 + g + (s&1)*8;
            #pragma unroll
            for (int d = 0; d < 4; d++)
                if (d < R) atomicAdd(&red[row*4 + d], part[s][d]);
        }
    }
    __syncthreads();
    if (tid < 128) {
        for (int d = 0; d < R; d++)
            outp[(long)(m0 + tid)*ostride + ooff + d] = red[tid*4 + d];
    }
}

// ---------------- GEMM kernels ----------------
__global__ __launch_bounds__(256,1) void tc_musig(
    const float* x, const float* muW1, const float* mub1, const float* muW2,
    const float* sgW1, const float* sgb1, const float* sgW2, float* ms)
{
    if (blockIdx.y == 0)
        gemm_core(x, Tc, muW1, 64, 1, mub1, nullptr, nullptr, nullptr, 0, 0, muW2, 4, ms, 8, 0);
    else
        gemm_core(x, Tc, sgW1, 64, 1, sgb1, nullptr, nullptr, nullptr, 0, 0, sgW2, 4, ms, 8, 4);
}

__global__ __launch_bounds__(256,1) void tc_wg(
    const float* eps, const float* wgW1, const float* wgb1, const float* wgW2,
    const float* Sp, const float* spmu, const float* spsg, float* lg)
{
    gemm_core(eps, Tc, wgW1, 64, 1, wgb1, Sp, spmu, spsg, 1, 0, wgW2, 1, lg, 1, 0);
}

struct FitArgs { const float *W1[4], *b1[4], *W2[4]; };

__global__ __launch_bounds__(256,1) void tc_fit(
    const float* eps, FitArgs fa, const float* Sbase,
    const float* spmu, const float* spsg, float* cf)
{
    int i = blockIdx.y;
    int R   = (i == 2) ? 3 : ((i == 1) ? 2 : 1);
    int off = (i == 0) ? 0 : (i == 1) ? 1 : (i == 2) ? 3 : 6;
    gemm_core(eps + i*Tc, 4*Tc, fa.W1[i], Fc, 12, fa.b1[i], Sbase + 64 + i*Fc,
              spmu, spsg, 4, i, fa.W2[i], R, cf, 8, off);
}

// ---------------- small kernels ----------------
__global__ void rowsum_kernel(const float* __restrict__ W, float* __restrict__ S, int rows){
    int warp = (blockIdx.x * blockDim.x + threadIdx.x) >> 5;
    int lane = threadIdx.x & 31;
    if (warp >= rows) return;
    const float* row = W + (long)warp * Tc;
    float s = 0.f;
    for (int j = lane; j < Tc; j += 32) s += row[j];
    #pragma unroll
    for (int o = 16; o; o >>= 1) s += __shfl_xor_sync(0xffffffffu, s, o);
    if (lane == 0) S[warp] = s;
}

__global__ void softplus_k(const float* __restrict__ mub2, const float* __restrict__ sgb2){
    int i = blockIdx.x*256 + threadIdx.x;
    if (i >= BNT*4) return;
    int row = i >> 2, k = i & 3;
    g_spmu[i] = softplus_f(g_ms[row*8 + k]     + mub2[k]);
    g_spsg[i] = softplus_f(g_ms[row*8 + 4 + k] + sgb2[k]);
}

__global__ void softmax_k(){
    int bn = blockIdx.x*256 + threadIdx.x;
    if (bn >= BNT) return;
    float a = g_lg[bn*4+0], b = g_lg[bn*4+1], c = g_lg[bn*4+2], d = g_lg[bn*4+3];
    float m = fmaxf(fmaxf(a,b), fmaxf(c,d));
    float e0 = expf(a-m), e1 = expf(b-m), e2 = expf(c-m), e3 = expf(d-m);
    float inv = 1.f/(e0+e1+e2+e3);
    g_w[bn*4+0] = e0*inv; g_w[bn*4+1] = e1*inv;
    g_w[bn*4+2] = e2*inv; g_w[bn*4+3] = e3*inv;
}

#define FCHUNK 48
__global__ void final_kernel(float* __restrict__ out,
                             const float* __restrict__ b2_0, const float* __restrict__ b2_1,
                             const float* __restrict__ b2_2, const float* __restrict__ b2_3){
    int b  = blockIdx.y;
    int f0 = blockIdx.x * FCHUNK;
    int n  = threadIdx.x;
    int bn = b * Nch + n;
    float w0 = g_w[bn*4+0], w1 = g_w[bn*4+1], w2 = g_w[bn*4+2], w3 = g_w[bn*4+3];
    float c0 = g_coef[bn*8+0] + b2_0[0];
    float c1 = g_coef[bn*8+1] + b2_1[0], c2 = g_coef[bn*8+2] + b2_1[1];
    float c3 = g_coef[bn*8+3] + b2_2[0], c4 = g_coef[bn*8+4] + b2_2[1], c5 = g_coef[bn*8+5] + b2_2[2];
    float c6 = g_coef[bn*8+6] + b2_3[0];
    #pragma unroll 4
    for (int fi = 0; fi < FCHUNK; fi++) {
        int f = f0 + fi;
        float tt = (float)f * (1.f/719.f);
        float t2 = tt*tt, t3 = t2*tt;
        float p0 = c0 + 0.5f*tt;
        float p1 = c1 + c2*tt + 0.5f*t2;
        float p2 = c3 + c4*tt + c5*t2 + 0.5f*t3;
        float p3 = c6 - 0.5f*tt;
        out[((long)b*Fc + f)*Nch + n] = w0*p0 + w1*p1 + w2*p2 + w3*p3;
    }
}

// ---------------- launch ----------------
extern "C" void kernel_launch(void* const* d_in, const int* in_sizes, int n_in,
                              void* d_out, int out_size)
{
    const float* x     = (const float*)d_in[0];
    const float* eps   = (const float*)d_in[1];
    const float* muW1  = (const float*)d_in[2];
    const float* mub1  = (const float*)d_in[3];
    const float* muW2  = (const float*)d_in[4];
    const float* mub2  = (const float*)d_in[5];
    const float* sgW1  = (const float*)d_in[6];
    const float* sgb1  = (const float*)d_in[7];
    const float* sgW2  = (const float*)d_in[8];
    const float* sgb2  = (const float*)d_in[9];
    const float* wgW1  = (const float*)d_in[10];
    const float* wgb1  = (const float*)d_in[11];
    const float* wgW2  = (const float*)d_in[12];
    // d_in[13] = wgb2 (cancels in softmax)
    FitArgs fa;
    fa.W1[0] = (const float*)d_in[14]; fa.b1[0] = (const float*)d_in[15]; fa.W2[0] = (const float*)d_in[16];
    fa.W1[1] = (const float*)d_in[18]; fa.b1[1] = (const float*)d_in[19]; fa.W2[1] = (const float*)d_in[20];
    fa.W1[2] = (const float*)d_in[22]; fa.b1[2] = (const float*)d_in[23]; fa.W2[2] = (const float*)d_in[24];
    fa.W1[3] = (const float*)d_in[26]; fa.b1[3] = (const float*)d_in[27]; fa.W2[3] = (const float*)d_in[28];
    const float* fb2[4] = {(const float*)d_in[17], (const float*)d_in[21],
                           (const float*)d_in[25], (const float*)d_in[29]};
    float* out = (float*)d_out;

    float* ms;  cudaGetSymbolAddress((void**)&ms,  g_ms);
    float* spm; cudaGetSymbolAddress((void**)&spm, g_spmu);
    float* sps; cudaGetSymbolAddress((void**)&sps, g_spsg);
    float* lg;  cudaGetSymbolAddress((void**)&lg,  g_lg);
    float* cf;  cudaGetSymbolAddress((void**)&cf,  g_coef);
    float* Sp;  cudaGetSymbolAddress((void**)&Sp,  g_S);

    // rowsums (wg + 4 fitters)
    rowsum_kernel<<<(64*32 + 255)/256, 256>>>(wgW1, Sp, 64);
    for (int i = 0; i < 4; i++)
        rowsum_kernel<<<(Fc*32 + 255)/256, 256>>>(fa.W1[i], Sp + 64 + i*Fc, Fc);

    // mu / sigma
    {
        dim3 grid(BNT/128, 2);
        tc_musig<<<grid, 256>>>(x, muW1, mub1, muW2, sgW1, sgb1, sgW2, ms);
    }
    softplus_k<<<(BNT*4 + 255)/256, 256>>>(mub2, sgb2);

    // wg
    tc_wg<<<(BNT*4)/128, 256>>>(eps, wgW1, wgb1, wgW2, Sp, spm, sps, lg);
    softmax_k<<<(BNT + 255)/256, 256>>>();

    // fitters (all 4 in one launch)
    {
        dim3 grid(BNT/128, 4);
        tc_fit<<<grid, 256>>>(eps, fa, Sp, spm, sps, cf);
    }

    // final mixture + transpose
    {
        dim3 grid(Fc/FCHUNK, Bc);
        final_kernel<<<grid, 128>>>(out, fb2[0], fb2[1], fb2[2], fb2[3]);
    }
}

// round 10
// speedup vs baseline: 2.6191x; 1.3067x over previous
#include <cuda_runtime.h>
#include <cuda_bf16.h>
#include <math.h>
#include <stdint.h>

#define Tc   336
#define BNT  16384
#define Fc   720
#define Nch  128
#define Bc   128
#define KC   48          // k-cols per smem stage
#define NSTG 7           // 336/48
#define RSTR 112         // smem row stride bytes (48 bf16 = 96B + 16 pad; 112/16=7 coprime 8)

// ---------------- scratch globals ----------------
__device__ float g_ms[BNT*8];
__device__ float g_spmu[BNT*4];
__device__ float g_spsg[BNT*4];
__device__ float g_w[BNT*4];
__device__ float g_coef[BNT*8];
__device__ float g_S[64 + 4*Fc];

__device__ __forceinline__ float softplus_f(float x){
    return fmaxf(x,0.f) + log1pf(expf(-fabsf(x)));
}
__device__ __forceinline__ uint32_t su32(const void* p){
    uint32_t a;
    asm("{ .reg .u64 t; cvta.to.shared.u64 t, %1; cvt.u32.u64 %0, t; }" : "=r"(a) : "l"(p));
    return a;
}

#define LDSM4(r, a) asm volatile( \
    "ldmatrix.sync.aligned.m8n8.x4.shared.b16 {%0,%1,%2,%3}, [%4];" \
    : "=r"((r)[0]), "=r"((r)[1]), "=r"((r)[2]), "=r"((r)[3]) : "r"(a))
#define MMA(c, a, b) asm volatile( \
    "mma.sync.aligned.m16n8k16.row.col.f32.bf16.bf16.f32 " \
    "{%0,%1,%2,%3}, {%4,%5,%6,%7}, {%8,%9}, {%0,%1,%2,%3};" \
    : "+f"((c)[0]), "+f"((c)[1]), "+f"((c)[2]), "+f"((c)[3]) \
    : "r"((a)[0]), "r"((a)[1]), "r"((a)[2]), "r"((a)[3]), "r"((b)[0]), "r"((b)[1]))

__device__ __forceinline__ void cvt_split(float4 v, uint2& h, uint2& lo){
    __nv_bfloat162 h01 = __floats2bfloat162_rn(v.x, v.y);
    __nv_bfloat162 h23 = __floats2bfloat162_rn(v.z, v.w);
    float2 f01 = __bfloat1622float2(h01), f23 = __bfloat1622float2(h23);
    __nv_bfloat162 l01 = __floats2bfloat162_rn(v.x - f01.x, v.y - f01.y);
    __nv_bfloat162 l23 = __floats2bfloat162_rn(v.z - f23.x, v.w - f23.y);
    h  = make_uint2(*(uint32_t*)&h01, *(uint32_t*)&h23);
    lo = make_uint2(*(uint32_t*)&l01, *(uint32_t*)&l23);
}

// =====================================================================
// Double-buffered split-bf16 mma.sync GEMM + fused reduce epilogue.
//   acc[m,n] = A[m,:].W1[n,:]  (K=336)
//   h = relu(b1[n] + smu[m]*S[n] + ssg[m]*acc)
//   WMODE 0: out[m*ostride+ooff+d] = sum_n h*W2[d,n]
//   WMODE 1: logits -> softmax over groups of 4 rows -> out (g_w)
// =====================================================================
template<int NTILE, int RT, int WMODE>
__device__ __forceinline__ void gemm_core(
    const float* __restrict__ A, int lda,
    const float* __restrict__ W1, int Ncols, int n_nt,
    const float* __restrict__ b1, const float* __restrict__ S,
    const float* __restrict__ spmu, const float* __restrict__ spsg,
    int sp_mul, int sp_add,
    const float* __restrict__ W2, int R,
    float* __restrict__ outp, int ostride, int ooff,
    int m0, char* smem)
{
    constexpr int AHALF = 128*RSTR;            // bytes per A half-tile
    constexpr int BHALF = NTILE*RSTR;
    constexpr int BUFSZ = 2*AHALF + 2*BHALF;   // one stage buffer (A hi/lo + B hi/lo)
    constexpr int NB4   = (NTILE*12)/256;      // B float4 per thread per stage
    constexpr int NJ    = NTILE/32;            // n8 tiles per warp
    constexpr int NPW   = NTILE/4;             // N cols per warp

    const int tid = threadIdx.x;
    const int wid = tid >> 5, lane = tid & 31;
    const int g = lane >> 2, l = lane & 3;
    const int wm = wid >> 2, wn = wid & 3;
    const uint32_t sb = su32(smem);
    float* stg = (float*)(smem + 2*BUFSZ);
    float* red = (float*)(smem + 2*BUFSZ + (2+RT)*NTILE*4);

    if (tid < 128) ((float4*)red)[tid] = make_float4(0.f,0.f,0.f,0.f);

    float part[8][RT];
    #pragma unroll
    for (int s = 0; s < 8; s++)
        #pragma unroll
        for (int d = 0; d < RT; d++) part[s][d] = 0.f;

    float4 pa[6], pb[NB4];

    auto ldgA = [&](int kc){
        #pragma unroll
        for (int it = 0; it < 6; it++){
            int q = tid + it*256; int r = q/12, cq = q - r*12;
            pa[it] = *(const float4*)(A + (long)(m0 + r)*lda + kc*KC + cq*4);
        }
    };
    auto ldgB = [&](int nt, int kc){
        #pragma unroll
        for (int it = 0; it < NB4; it++){
            int q = tid + it*256; int n = q/12, cq = q - n*12;
            int gn = nt*NTILE + n;
            pb[it] = (gn < Ncols) ? *(const float4*)(W1 + (long)gn*Tc + kc*KC + cq*4)
                                  : make_float4(0.f,0.f,0.f,0.f);
        }
    };
    auto sts = [&](int buf){
        char* bb = smem + buf*BUFSZ;
        #pragma unroll
        for (int it = 0; it < 6; it++){
            int q = tid + it*256; int r = q/12, cq = q - r*12;
            uint2 h, lo; cvt_split(pa[it], h, lo);
            *(uint2*)(bb + r*RSTR + cq*8) = h;
            *(uint2*)(bb + AHALF + r*RSTR + cq*8) = lo;
        }
        #pragma unroll
        for (int it = 0; it < NB4; it++){
            int q = tid + it*256; int n = q/12, cq = q - n*12;
            uint2 h, lo; cvt_split(pb[it], h, lo);
            *(uint2*)(bb + 2*AHALF + n*RSTR + cq*8) = h;
            *(uint2*)(bb + 2*AHALF + BHALF + n*RSTR + cq*8) = lo;
        }
    };

    for (int nt = 0; nt < n_nt; nt++){
        __syncthreads();   // stg reuse + buf0 reuse safety
        // staging: b1 / S / W2 rows for this n-tile
        for (int idx = tid; idx < NTILE*(2+RT); idx += 256){
            int n = idx % NTILE, row = idx / NTILE;
            int gn = nt*NTILE + n;
            float v = 0.f;
            if (gn < Ncols){
                if (row == 0)           v = b1[gn];
                else if (row == 1)      v = (S != nullptr) ? S[gn] : 0.f;
                else if (row - 2 < R)   v = W2[(row-2)*Ncols + gn];
            }
            stg[row*NTILE + n] = v;
        }

        float acc[4][NJ][4];
        #pragma unroll
        for (int i = 0; i < 4; i++)
            #pragma unroll
            for (int j = 0; j < NJ; j++)
                #pragma unroll
                for (int e = 0; e < 4; e++) acc[i][j][e] = 0.f;

        ldgA(0); ldgB(nt, 0);
        sts(0);
        __syncthreads();

        for (int kc = 0; kc < NSTG; kc++){
            if (kc + 1 < NSTG){ ldgA(kc+1); ldgB(nt, kc+1); }
            // ---- MMA over buffer kc&1 ----
            {
                const uint32_t base = sb + (kc & 1)*BUFSZ;
                #pragma unroll
                for (int ks = 0; ks < 3; ks++){
                    uint32_t ah[4][4], al[4][4];
                    #pragma unroll
                    for (int i = 0; i < 4; i++){
                        int row = wm*64 + i*16 + (lane & 15);
                        uint32_t ad = base + row*RSTR + ks*32 + ((lane>>4)<<4);
                        LDSM4(ah[i], ad);
                        LDSM4(al[i], ad + AHALF);
                    }
                    uint32_t bh[NJ][2], bl[NJ][2];
                    #pragma unroll
                    for (int p = 0; p < NJ/2; p++){
                        int rowb = wn*NPW + p*16 + ((lane>>4)<<3) + (lane & 7);
                        uint32_t ad = base + 2*AHALF + rowb*RSTR + ks*32 + (((lane>>3)&1)<<4);
                        uint32_t t[4];
                        LDSM4(t, ad);
                        bh[2*p][0]=t[0]; bh[2*p][1]=t[1]; bh[2*p+1][0]=t[2]; bh[2*p+1][1]=t[3];
                        LDSM4(t, ad + BHALF);
                        bl[2*p][0]=t[0]; bl[2*p][1]=t[1]; bl[2*p+1][0]=t[2]; bl[2*p+1][1]=t[3];
                    }
                    #pragma unroll
                    for (int i = 0; i < 4; i++)
                        #pragma unroll
                        for (int j = 0; j < NJ; j++){
                            MMA(acc[i][j], ah[i], bh[j]);
                            MMA(acc[i][j], ah[i], bl[j]);
                            MMA(acc[i][j], al[i], bh[j]);
                        }
                }
            }
            if (kc + 1 < NSTG) sts((kc+1) & 1);
            __syncthreads();
        }

        // ---- epilogue: relu + affine + partial n-reduction ----
        float smu8[8], ssg8[8];
        #pragma unroll
        for (int s = 0; s < 8; s++){
            if (spmu != nullptr){
                int row = m0 + wm*64 + (s>>1)*16 + g + (s&1)*8;
                smu8[s] = spmu[row*sp_mul + sp_add];
                ssg8[s] = spsg[row*sp_mul + sp_add];
            } else { smu8[s] = 0.f; ssg8[s] = 1.f; }
        }
        #pragma unroll
        for (int i = 0; i < 4; i++)
            #pragma unroll
            for (int j = 0; j < NJ; j++)
                #pragma unroll
                for (int e = 0; e < 4; e++){
                    int nl = wn*NPW + j*8 + 2*l + (e&1);
                    int s  = i*2 + (e>>1);
                    float hv = fmaxf(stg[nl] + smu8[s]*stg[NTILE+nl] + ssg8[s]*acc[i][j][e], 0.f);
                    #pragma unroll
                    for (int d = 0; d < RT; d++)
                        part[s][d] += stg[(2+d)*NTILE + nl] * hv;
                }
    }

    // cross-lane (l) reduce, then cross-warp via smem atomics
    #pragma unroll
    for (int s = 0; s < 8; s++)
        #pragma unroll
        for (int d = 0; d < RT; d++){
            float v = part[s][d];
            v += __shfl_xor_sync(0xffffffffu, v, 1);
            v += __shfl_xor_sync(0xffffffffu, v, 2);
            part[s][d] = v;
        }
    if (l == 0){
        #pragma unroll
        for (int s = 0; s < 8; s++){
            int rl = wm*64 + (s>>1)*16 + g + (s&1)*8;
            #pragma unroll
            for (int d = 0; d < RT; d++)
                if (d < R) atomicAdd(&red[rl*4 + d], part[s][d]);
        }
    }
    __syncthreads();
    if (WMODE == 0){
        if (tid < 128)
            for (int d = 0; d < R; d++)
                outp[(long)(m0 + tid)*ostride + ooff + d] = red[tid*4 + d];
    } else {
        if (tid < 32){
            float lg0 = red[(tid*4+0)*4], lg1 = red[(tid*4+1)*4];
            float lg2 = red[(tid*4+2)*4], lg3 = red[(tid*4+3)*4];
            float m = fmaxf(fmaxf(lg0,lg1), fmaxf(lg2,lg3));
            float e0 = expf(lg0-m), e1 = expf(lg1-m), e2 = expf(lg2-m), e3 = expf(lg3-m);
            float inv = 1.f/(e0+e1+e2+e3);
            outp[m0 + tid*4 + 0] = e0*inv; outp[m0 + tid*4 + 1] = e1*inv;
            outp[m0 + tid*4 + 2] = e2*inv; outp[m0 + tid*4 + 3] = e3*inv;
        }
    }
}

// ---------------- kernels ----------------
struct MainArgs {
    const float *wgW1, *wgb1, *wgW2, *Sp, *spm, *sps;
    const float *fW1[4], *fb1[4], *fW2[4];
    float *gw, *cf;
};

__global__ __launch_bounds__(256,1) void main_k(const float* __restrict__ eps, MainArgs a)
{
    extern __shared__ char smem[];
    int bid = blockIdx.x;
    if (bid < 512){
        gemm_core<64,1,1>(eps, Tc, a.wgW1, 64, 1, a.wgb1, a.Sp,
                          a.spm, a.sps, 1, 0, a.wgW2, 1,
                          a.gw, 1, 0, bid*128, smem);
    } else {
        int b2 = bid - 512;
        int i  = b2 >> 7;
        int m0 = (b2 & 127)*128;
        int R   = (i == 2) ? 3 : ((i == 1) ? 2 : 1);
        int off = (i == 0) ? 0 : (i == 1) ? 1 : (i == 2) ? 3 : 6;
        gemm_core<128,3,0>(eps + i*Tc, 4*Tc, a.fW1[i], Fc, 6, a.fb1[i],
                           a.Sp + 64 + i*Fc, a.spm, a.sps, 4, i,
                           a.fW2[i], R, a.cf, 8, off, m0, smem);
    }
}

__global__ __launch_bounds__(256,1) void musig_k(
    const float* __restrict__ x,
    const float* muW1, const float* mub1, const float* muW2,
    const float* sgW1, const float* sgb1, const float* sgW2, float* ms)
{
    extern __shared__ char smem[];
    if (blockIdx.y == 0)
        gemm_core<64,4,0>(x, Tc, muW1, 64, 1, mub1, nullptr, nullptr, nullptr, 0, 0,
                          muW2, 4, ms, 8, 0, blockIdx.x*128, smem);
    else
        gemm_core<64,4,0>(x, Tc, sgW1, 64, 1, sgb1, nullptr, nullptr, nullptr, 0, 0,
                          sgW2, 4, ms, 8, 4, blockIdx.x*128, smem);
}

struct RowArgs { const float *wg, *f[4]; };
__global__ void rowsum_all(RowArgs ra, float* __restrict__ S)
{
    int r = (blockIdx.x * blockDim.x + threadIdx.x) >> 5;
    int lane = threadIdx.x & 31;
    if (r >= 64 + 4*Fc) return;
    const float* row;
    if (r < 64) row = ra.wg + (long)r*Tc;
    else { int i = (r-64)/Fc, rr = (r-64) - i*Fc; row = ra.f[i] + (long)rr*Tc; }
    float s = 0.f;
    for (int j = lane; j < Tc; j += 32) s += row[j];
    #pragma unroll
    for (int o = 16; o; o >>= 1) s += __shfl_xor_sync(0xffffffffu, s, o);
    if (lane == 0) S[r] = s;
}

__global__ void softplus_k(const float* __restrict__ mub2, const float* __restrict__ sgb2){
    int i = blockIdx.x*256 + threadIdx.x;
    if (i >= BNT*4) return;
    int row = i >> 2, k = i & 3;
    g_spmu[i] = softplus_f(g_ms[row*8 + k]     + mub2[k]);
    g_spsg[i] = softplus_f(g_ms[row*8 + 4 + k] + sgb2[k]);
}

#define FCHUNK 48
__global__ void final_kernel(float* __restrict__ out,
                             const float* __restrict__ b2_0, const float* __restrict__ b2_1,
                             const float* __restrict__ b2_2, const float* __restrict__ b2_3){
    int b  = blockIdx.y;
    int f0 = blockIdx.x * FCHUNK;
    int n  = threadIdx.x;
    int bn = b * Nch + n;
    float w0 = g_w[bn*4+0], w1 = g_w[bn*4+1], w2 = g_w[bn*4+2], w3 = g_w[bn*4+3];
    float c0 = g_coef[bn*8+0] + b2_0[0];
    float c1 = g_coef[bn*8+1] + b2_1[0], c2 = g_coef[bn*8+2] + b2_1[1];
    float c3 = g_coef[bn*8+3] + b2_2[0], c4 = g_coef[bn*8+4] + b2_2[1], c5 = g_coef[bn*8+5] + b2_2[2];
    float c6 = g_coef[bn*8+6] + b2_3[0];
    #pragma unroll 4
    for (int fi = 0; fi < FCHUNK; fi++) {
        int f = f0 + fi;
        float tt = (float)f * (1.f/719.f);
        float t2 = tt*tt, t3 = t2*tt;
        float p0 = c0 + 0.5f*tt;
        float p1 = c1 + c2*tt + 0.5f*t2;
        float p2 = c3 + c4*tt + c5*t2 + 0.5f*t3;
        float p3 = c6 - 0.5f*tt;
        out[((long)b*Fc + f)*Nch + n] = w0*p0 + w1*p1 + w2*p2 + w3*p3;
    }
}

// ---------------- launch ----------------
extern "C" void kernel_launch(void* const* d_in, const int* in_sizes, int n_in,
                              void* d_out, int out_size)
{
    const float* x     = (const float*)d_in[0];
    const float* eps   = (const float*)d_in[1];
    const float* muW1  = (const float*)d_in[2];
    const float* mub1  = (const float*)d_in[3];
    const float* muW2  = (const float*)d_in[4];
    const float* mub2  = (const float*)d_in[5];
    const float* sgW1  = (const float*)d_in[6];
    const float* sgb1  = (const float*)d_in[7];
    const float* sgW2  = (const float*)d_in[8];
    const float* sgb2  = (const float*)d_in[9];
    const float* wgW1  = (const float*)d_in[10];
    const float* wgb1  = (const float*)d_in[11];
    const float* wgW2  = (const float*)d_in[12];
    // d_in[13] = wgb2 (cancels in softmax)
    const float* fb2[4] = {(const float*)d_in[17], (const float*)d_in[21],
                           (const float*)d_in[25], (const float*)d_in[29]};
    float* out = (float*)d_out;

    float* ms;  cudaGetSymbolAddress((void**)&ms,  g_ms);
    float* spm; cudaGetSymbolAddress((void**)&spm, g_spmu);
    float* sps; cudaGetSymbolAddress((void**)&sps, g_spsg);
    float* gw;  cudaGetSymbolAddress((void**)&gw,  g_w);
    float* cf;  cudaGetSymbolAddress((void**)&cf,  g_coef);
    float* Sp;  cudaGetSymbolAddress((void**)&Sp,  g_S);

    MainArgs a;
    a.wgW1 = wgW1; a.wgb1 = wgb1; a.wgW2 = wgW2;
    a.Sp = Sp; a.spm = spm; a.sps = sps; a.gw = gw; a.cf = cf;
    a.fW1[0] = (const float*)d_in[14]; a.fb1[0] = (const float*)d_in[15]; a.fW2[0] = (const float*)d_in[16];
    a.fW1[1] = (const float*)d_in[18]; a.fb1[1] = (const float*)d_in[19]; a.fW2[1] = (const float*)d_in[20];
    a.fW1[2] = (const float*)d_in[22]; a.fb1[2] = (const float*)d_in[23]; a.fW2[2] = (const float*)d_in[24];
    a.fW1[3] = (const float*)d_in[26]; a.fb1[3] = (const float*)d_in[27]; a.fW2[3] = (const float*)d_in[28];

    RowArgs ra;
    ra.wg = wgW1;
    for (int i = 0; i < 4; i++) ra.f[i] = a.fW1[i];

    // smem: NT=128/RT=3: 2*(2*14336+2*128*112) + 5*128*4 + 2048 = 119296
    //       NT=64 /RT=4: 2*(2*14336+2* 64*112) + 6* 64*4 + 2048 = 89600
    const int SMEM_MAIN  = 119296;
    const int SMEM_MUSIG = 89600;
    static bool attr_set = false;
    if (!attr_set){
        cudaFuncSetAttribute(main_k,  cudaFuncAttributeMaxDynamicSharedMemorySize, SMEM_MAIN);
        cudaFuncSetAttribute(musig_k, cudaFuncAttributeMaxDynamicSharedMemorySize, SMEM_MUSIG);
        attr_set = true;
    }

    // rowsums (all 2944 rows in one launch)
    rowsum_all<<<(2944*32 + 255)/256, 256>>>(ra, Sp);

    // mu / sigma second-layer raw sums
    {
        dim3 grid(BNT/128, 2);
        musig_k<<<grid, 256, SMEM_MUSIG>>>(x, muW1, mub1, muW2, sgW1, sgb1, sgW2, ms);
    }
    softplus_k<<<(BNT*4 + 255)/256, 256>>>(mub2, sgb2);

    // wg (512 CTAs) + 4 fitters (512 CTAs) in one launch
    main_k<<<1024, 256, SMEM_MAIN>>>(eps, a);

    // final mixture + transpose
    {
        dim3 grid(Fc/FCHUNK, Bc);
        final_kernel<<<grid, 128>>>(out, fb2[0], fb2[1], fb2[2], fb2[3]);
    }
}

// round 11
// speedup vs baseline: 2.6427x; 1.0090x over previous
#include <cuda_runtime.h>
#include <cuda_bf16.h>
#include <math.h>
#include <stdint.h>

#define Tc   336
#define BNT  16384
#define Fc   720
#define Nch  128
#define Bc   128
#define KC   48          // k-cols per smem stage
#define NSTG 7           // 336/48
#define RSTR 112         // smem row stride bytes (48 bf16 = 96B + 16 pad; 112/16=7 coprime 8)

// ---------------- scratch globals ----------------
__device__ float g_ms[BNT*8];
__device__ float g_spmu[BNT*4];
__device__ float g_spsg[BNT*4];
__device__ float g_w[BNT*4];
__device__ float g_coef[BNT*8];
__device__ float g_S[64 + 4*Fc];

__device__ __forceinline__ float softplus_f(float x){
    return fmaxf(x,0.f) + log1pf(expf(-fabsf(x)));
}
__device__ __forceinline__ uint32_t su32(const void* p){
    uint32_t a;
    asm("{ .reg .u64 t; cvta.to.shared.u64 t, %1; cvt.u32.u64 %0, t; }" : "=r"(a) : "l"(p));
    return a;
}

#define LDSM4(r, a) asm volatile( \
    "ldmatrix.sync.aligned.m8n8.x4.shared.b16 {%0,%1,%2,%3}, [%4];" \
    : "=r"((r)[0]), "=r"((r)[1]), "=r"((r)[2]), "=r"((r)[3]) : "r"(a))
#define MMA(c, a, b) asm volatile( \
    "mma.sync.aligned.m16n8k16.row.col.f32.bf16.bf16.f32 " \
    "{%0,%1,%2,%3}, {%4,%5,%6,%7}, {%8,%9}, {%0,%1,%2,%3};" \
    : "+f"((c)[0]), "+f"((c)[1]), "+f"((c)[2]), "+f"((c)[3]) \
    : "r"((a)[0]), "r"((a)[1]), "r"((a)[2]), "r"((a)[3]), "r"((b)[0]), "r"((b)[1]))

__device__ __forceinline__ void cvt_split(float4 v, uint2& h, uint2& lo){
    __nv_bfloat162 h01 = __floats2bfloat162_rn(v.x, v.y);
    __nv_bfloat162 h23 = __floats2bfloat162_rn(v.z, v.w);
    float2 f01 = __bfloat1622float2(h01), f23 = __bfloat1622float2(h23);
    __nv_bfloat162 l01 = __floats2bfloat162_rn(v.x - f01.x, v.y - f01.y);
    __nv_bfloat162 l23 = __floats2bfloat162_rn(v.z - f23.x, v.w - f23.y);
    h  = make_uint2(*(uint32_t*)&h01, *(uint32_t*)&h23);
    lo = make_uint2(*(uint32_t*)&l01, *(uint32_t*)&l23);
}

// =====================================================================
// Double-buffered split-bf16 mma.sync GEMM + fused reduce epilogue,
// with STS interleaved between MMA k-steps so the tensor pipe stays busy.
//   acc[m,n] = A[m,:].W1[n,:]  (K=336)
//   h = relu(b1[n] + smu[m]*S[n] + ssg[m]*acc)
//   WMODE 0: out[m*ostride+ooff+d] = sum_n h*W2[d,n]
//   WMODE 1: logits -> softmax over groups of 4 rows -> out (g_w)
// =====================================================================
template<int NTILE, int RT, int WMODE>
__device__ __forceinline__ void gemm_core(
    const float* __restrict__ A, int lda,
    const float* __restrict__ W1, int Ncols, int n_nt,
    const float* __restrict__ b1, const float* __restrict__ S,
    const float* __restrict__ spmu, const float* __restrict__ spsg,
    int sp_mul, int sp_add,
    const float* __restrict__ W2, int R,
    float* __restrict__ outp, int ostride, int ooff,
    int m0, char* smem)
{
    constexpr int AHALF = 128*RSTR;            // bytes per A half-tile
    constexpr int BHALF = NTILE*RSTR;
    constexpr int BUFSZ = 2*AHALF + 2*BHALF;   // one stage buffer (A hi/lo + B hi/lo)
    constexpr int NB4   = (NTILE*12)/256;      // B float4 per thread per stage
    constexpr int NJ    = NTILE/32;            // n8 tiles per warp
    constexpr int NPW   = NTILE/4;             // N cols per warp

    const int tid = threadIdx.x;
    const int wid = tid >> 5, lane = tid & 31;
    const int g = lane >> 2, l = lane & 3;
    const int wm = wid >> 2, wn = wid & 3;
    const uint32_t sb = su32(smem);
    float* stg = (float*)(smem + 2*BUFSZ);
    float* red = (float*)(smem + 2*BUFSZ + (2+RT)*NTILE*4);

    if (tid < 128) ((float4*)red)[tid] = make_float4(0.f,0.f,0.f,0.f);

    float part[8][RT];
    #pragma unroll
    for (int s = 0; s < 8; s++)
        #pragma unroll
        for (int d = 0; d < RT; d++) part[s][d] = 0.f;

    float4 pa[6], pb[NB4];

    auto ldgA = [&](int kc){
        #pragma unroll
        for (int it = 0; it < 6; it++){
            int q = tid + it*256; int r = q/12, cq = q - r*12;
            pa[it] = *(const float4*)(A + (long)(m0 + r)*lda + kc*KC + cq*4);
        }
    };
    auto ldgB = [&](int nt, int kc){
        #pragma unroll
        for (int it = 0; it < NB4; it++){
            int q = tid + it*256; int n = q/12, cq = q - n*12;
            int gn = nt*NTILE + n;
            pb[it] = (gn < Ncols) ? *(const float4*)(W1 + (long)gn*Tc + kc*KC + cq*4)
                                  : make_float4(0.f,0.f,0.f,0.f);
        }
    };
    auto sts = [&](int buf){
        char* bb = smem + buf*BUFSZ;
        #pragma unroll
        for (int it = 0; it < 6; it++){
            int q = tid + it*256; int r = q/12, cq = q - r*12;
            uint2 h, lo; cvt_split(pa[it], h, lo);
            *(uint2*)(bb + r*RSTR + cq*8) = h;
            *(uint2*)(bb + AHALF + r*RSTR + cq*8) = lo;
        }
        #pragma unroll
        for (int it = 0; it < NB4; it++){
            int q = tid + it*256; int n = q/12, cq = q - n*12;
            uint2 h, lo; cvt_split(pb[it], h, lo);
            *(uint2*)(bb + 2*AHALF + n*RSTR + cq*8) = h;
            *(uint2*)(bb + 2*AHALF + BHALF + n*RSTR + cq*8) = lo;
        }
    };

    for (int nt = 0; nt < n_nt; nt++){
        __syncthreads();   // stg reuse + buf0 reuse safety
        // staging: b1 / S / W2 rows for this n-tile
        for (int idx = tid; idx < NTILE*(2+RT); idx += 256){
            int n = idx % NTILE, row = idx / NTILE;
            int gn = nt*NTILE + n;
            float v = 0.f;
            if (gn < Ncols){
                if (row == 0)           v = b1[gn];
                else if (row == 1)      v = (S != nullptr) ? S[gn] : 0.f;
                else if (row - 2 < R)   v = W2[(row-2)*Ncols + gn];
            }
            stg[row*NTILE + n] = v;
        }

        float acc[4][NJ][4];
        #pragma unroll
        for (int i = 0; i < 4; i++)
            #pragma unroll
            for (int j = 0; j < NJ; j++)
                #pragma unroll
                for (int e = 0; e < 4; e++) acc[i][j][e] = 0.f;

        ldgA(0); ldgB(nt, 0);
        sts(0);
        __syncthreads();

        // one MMA k-step (k16) over the given buffer
        auto mma_step = [&](uint32_t base, int ks){
            uint32_t ah[4][4], al[4][4];
            #pragma unroll
            for (int i = 0; i < 4; i++){
                int row = wm*64 + i*16 + (lane & 15);
                uint32_t ad = base + row*RSTR + ks*32 + ((lane>>4)<<4);
                LDSM4(ah[i], ad);
                LDSM4(al[i], ad + AHALF);
            }
            uint32_t bh[NJ][2], bl[NJ][2];
            #pragma unroll
            for (int p = 0; p < NJ/2; p++){
                int rowb = wn*NPW + p*16 + ((lane>>4)<<3) + (lane & 7);
                uint32_t ad = base + 2*AHALF + rowb*RSTR + ks*32 + (((lane>>3)&1)<<4);
                uint32_t t[4];
                LDSM4(t, ad);
                bh[2*p][0]=t[0]; bh[2*p][1]=t[1]; bh[2*p+1][0]=t[2]; bh[2*p+1][1]=t[3];
                LDSM4(t, ad + BHALF);
                bl[2*p][0]=t[0]; bl[2*p][1]=t[1]; bl[2*p+1][0]=t[2]; bl[2*p+1][1]=t[3];
            }
            #pragma unroll
            for (int i = 0; i < 4; i++)
                #pragma unroll
                for (int j = 0; j < NJ; j++){
                    MMA(acc[i][j], ah[i], bh[j]);
                    MMA(acc[i][j], ah[i], bl[j]);
                    MMA(acc[i][j], al[i], bh[j]);
                }
        };

        for (int kc = 0; kc < NSTG; kc++){
            const uint32_t base = sb + (kc & 1)*BUFSZ;
            const bool more = (kc + 1 < NSTG);
            if (more){ ldgA(kc+1); ldgB(nt, kc+1); }
            mma_step(base, 0);
            mma_step(base, 1);
            if (more) sts((kc+1) & 1);   // STS next buffer between MMA k-steps
            mma_step(base, 2);
            __syncthreads();
        }

        // ---- epilogue: relu + affine + partial n-reduction ----
        float smu8[8], ssg8[8];
        #pragma unroll
        for (int s = 0; s < 8; s++){
            if (spmu != nullptr){
                int row = m0 + wm*64 + (s>>1)*16 + g + (s&1)*8;
                smu8[s] = spmu[row*sp_mul + sp_add];
                ssg8[s] = spsg[row*sp_mul + sp_add];
            } else { smu8[s] = 0.f; ssg8[s] = 1.f; }
        }
        #pragma unroll
        for (int i = 0; i < 4; i++)
            #pragma unroll
            for (int j = 0; j < NJ; j++)
                #pragma unroll
                for (int e = 0; e < 4; e++){
                    int nl = wn*NPW + j*8 + 2*l + (e&1);
                    int s  = i*2 + (e>>1);
                    float hv = fmaxf(stg[nl] + smu8[s]*stg[NTILE+nl] + ssg8[s]*acc[i][j][e], 0.f);
                    #pragma unroll
                    for (int d = 0; d < RT; d++)
                        part[s][d] += stg[(2+d)*NTILE + nl] * hv;
                }
    }

    // cross-lane (l) reduce, then cross-warp via smem atomics
    #pragma unroll
    for (int s = 0; s < 8; s++)
        #pragma unroll
        for (int d = 0; d < RT; d++){
            float v = part[s][d];
            v += __shfl_xor_sync(0xffffffffu, v, 1);
            v += __shfl_xor_sync(0xffffffffu, v, 2);
            part[s][d] = v;
        }
    if (l == 0){
        #pragma unroll
        for (int s = 0; s < 8; s++){
            int rl = wm*64 + (s>>1)*16 + g + (s&1)*8;
            #pragma unroll
            for (int d = 0; d < RT; d++)
                if (d < R) atomicAdd(&red[rl*4 + d], part[s][d]);
        }
    }
    __syncthreads();
    if (WMODE == 0){
        if (tid < 128)
            for (int d = 0; d < R; d++)
                outp[(long)(m0 + tid)*ostride + ooff + d] = red[tid*4 + d];
    } else {
        if (tid < 32){
            float lg0 = red[(tid*4+0)*4], lg1 = red[(tid*4+1)*4];
            float lg2 = red[(tid*4+2)*4], lg3 = red[(tid*4+3)*4];
            float m = fmaxf(fmaxf(lg0,lg1), fmaxf(lg2,lg3));
            float e0 = expf(lg0-m), e1 = expf(lg1-m), e2 = expf(lg2-m), e3 = expf(lg3-m);
            float inv = 1.f/(e0+e1+e2+e3);
            outp[m0 + tid*4 + 0] = e0*inv; outp[m0 + tid*4 + 1] = e1*inv;
            outp[m0 + tid*4 + 2] = e2*inv; outp[m0 + tid*4 + 3] = e3*inv;
        }
    }
}

// ---------------- kernels ----------------
struct MainArgs {
    const float *wgW1, *wgb1, *wgW2, *Sp, *spm, *sps;
    const float *fW1[4], *fb1[4], *fW2[4];
    float *gw, *cf;
};

__global__ __launch_bounds__(256,1) void main_k(const float* __restrict__ eps, MainArgs a)
{
    extern __shared__ char smem[];
    int bid = blockIdx.x;
    if (bid < 512){
        gemm_core<64,1,1>(eps, Tc, a.wgW1, 64, 1, a.wgb1, a.Sp,
                          a.spm, a.sps, 1, 0, a.wgW2, 1,
                          a.gw, 1, 0, bid*128, smem);
    } else {
        int b2 = bid - 512;
        int i  = b2 >> 7;
        int m0 = (b2 & 127)*128;
        int R   = (i == 2) ? 3 : ((i == 1) ? 2 : 1);
        int off = (i == 0) ? 0 : (i == 1) ? 1 : (i == 2) ? 3 : 6;
        gemm_core<128,3,0>(eps + i*Tc, 4*Tc, a.fW1[i], Fc, 6, a.fb1[i],
                           a.Sp + 64 + i*Fc, a.spm, a.sps, 4, i,
                           a.fW2[i], R, a.cf, 8, off, m0, smem);
    }
}

__global__ __launch_bounds__(256,1) void musig_k(
    const float* __restrict__ x,
    const float* muW1, const float* mub1, const float* muW2,
    const float* sgW1, const float* sgb1, const float* sgW2, float* ms)
{
    extern __shared__ char smem[];
    if (blockIdx.y == 0)
        gemm_core<64,4,0>(x, Tc, muW1, 64, 1, mub1, nullptr, nullptr, nullptr, 0, 0,
                          muW2, 4, ms, 8, 0, blockIdx.x*128, smem);
    else
        gemm_core<64,4,0>(x, Tc, sgW1, 64, 1, sgb1, nullptr, nullptr, nullptr, 0, 0,
                          sgW2, 4, ms, 8, 4, blockIdx.x*128, smem);
}

struct RowArgs { const float *wg, *f[4]; };
__global__ void rowsum_all(RowArgs ra, float* __restrict__ S)
{
    int r = (blockIdx.x * blockDim.x + threadIdx.x) >> 5;
    int lane = threadIdx.x & 31;
    if (r >= 64 + 4*Fc) return;
    const float* row;
    if (r < 64) row = ra.wg + (long)r*Tc;
    else { int i = (r-64)/Fc, rr = (r-64) - i*Fc; row = ra.f[i] + (long)rr*Tc; }
    float s = 0.f;
    for (int j = lane; j < Tc; j += 32) s += row[j];
    #pragma unroll
    for (int o = 16; o; o >>= 1) s += __shfl_xor_sync(0xffffffffu, s, o);
    if (lane == 0) S[r] = s;
}

__global__ void softplus_k(const float* __restrict__ mub2, const float* __restrict__ sgb2){
    int i = blockIdx.x*256 + threadIdx.x;
    if (i >= BNT*4) return;
    int row = i >> 2, k = i & 3;
    g_spmu[i] = softplus_f(g_ms[row*8 + k]     + mub2[k]);
    g_spsg[i] = softplus_f(g_ms[row*8 + 4 + k] + sgb2[k]);
}

#define FCHUNK 48
__global__ void final_kernel(float* __restrict__ out,
                             const float* __restrict__ b2_0, const float* __restrict__ b2_1,
                             const float* __restrict__ b2_2, const float* __restrict__ b2_3){
    int b  = blockIdx.y;
    int f0 = blockIdx.x * FCHUNK;
    int n  = threadIdx.x;
    int bn = b * Nch + n;
    float w0 = g_w[bn*4+0], w1 = g_w[bn*4+1], w2 = g_w[bn*4+2], w3 = g_w[bn*4+3];
    float c0 = g_coef[bn*8+0] + b2_0[0];
    float c1 = g_coef[bn*8+1] + b2_1[0], c2 = g_coef[bn*8+2] + b2_1[1];
    float c3 = g_coef[bn*8+3] + b2_2[0], c4 = g_coef[bn*8+4] + b2_2[1], c5 = g_coef[bn*8+5] + b2_2[2];
    float c6 = g_coef[bn*8+6] + b2_3[0];
    #pragma unroll 4
    for (int fi = 0; fi < FCHUNK; fi++) {
        int f = f0 + fi;
        float tt = (float)f * (1.f/719.f);
        float t2 = tt*tt, t3 = t2*tt;
        float p0 = c0 + 0.5f*tt;
        float p1 = c1 + c2*tt + 0.5f*t2;
        float p2 = c3 + c4*tt + c5*t2 + 0.5f*t3;
        float p3 = c6 - 0.5f*tt;
        out[((long)b*Fc + f)*Nch + n] = w0*p0 + w1*p1 + w2*p2 + w3*p3;
    }
}

// ---------------- launch ----------------
extern "C" void kernel_launch(void* const* d_in, const int* in_sizes, int n_in,
                              void* d_out, int out_size)
{
    const float* x     = (const float*)d_in[0];
    const float* eps   = (const float*)d_in[1];
    const float* muW1  = (const float*)d_in[2];
    const float* mub1  = (const float*)d_in[3];
    const float* muW2  = (const float*)d_in[4];
    const float* mub2  = (const float*)d_in[5];
    const float* sgW1  = (const float*)d_in[6];
    const float* sgb1  = (const float*)d_in[7];
    const float* sgW2  = (const float*)d_in[8];
    const float* sgb2  = (const float*)d_in[9];
    const float* wgW1  = (const float*)d_in[10];
    const float* wgb1  = (const float*)d_in[11];
    const float* wgW2  = (const float*)d_in[12];
    // d_in[13] = wgb2 (cancels in softmax)
    const float* fb2[4] = {(const float*)d_in[17], (const float*)d_in[21],
                           (const float*)d_in[25], (const float*)d_in[29]};
    float* out = (float*)d_out;

    float* ms;  cudaGetSymbolAddress((void**)&ms,  g_ms);
    float* spm; cudaGetSymbolAddress((void**)&spm, g_spmu);
    float* sps; cudaGetSymbolAddress((void**)&sps, g_spsg);
    float* gw;  cudaGetSymbolAddress((void**)&gw,  g_w);
    float* cf;  cudaGetSymbolAddress((void**)&cf,  g_coef);
    float* Sp;  cudaGetSymbolAddress((void**)&Sp,  g_S);

    MainArgs a;
    a.wgW1 = wgW1; a.wgb1 = wgb1; a.wgW2 = wgW2;
    a.Sp = Sp; a.spm = spm; a.sps = sps; a.gw = gw; a.cf = cf;
    a.fW1[0] = (const float*)d_in[14]; a.fb1[0] = (const float*)d_in[15]; a.fW2[0] = (const float*)d_in[16];
    a.fW1[1] = (const float*)d_in[18]; a.fb1[1] = (const float*)d_in[19]; a.fW2[1] = (const float*)d_in[20];
    a.fW1[2] = (const float*)d_in[22]; a.fb1[2] = (const float*)d_in[23]; a.fW2[2] = (const float*)d_in[24];
    a.fW1[3] = (const float*)d_in[26]; a.fb1[3] = (const float*)d_in[27]; a.fW2[3] = (const float*)d_in[28];

    RowArgs ra;
    ra.wg = wgW1;
    for (int i = 0; i < 4; i++) ra.f[i] = a.fW1[i];

    // smem: NT=128/RT=3: 2*(2*14336+2*128*112) + 5*128*4 + 2048 = 119296
    //       NT=64 /RT=4: 2*(2*14336+2* 64*112) + 6* 64*4 + 2048 = 89600
    const int SMEM_MAIN  = 119296;
    const int SMEM_MUSIG = 89600;
    static bool attr_set = false;
    if (!attr_set){
        cudaFuncSetAttribute(main_k,  cudaFuncAttributeMaxDynamicSharedMemorySize, SMEM_MAIN);
        cudaFuncSetAttribute(musig_k, cudaFuncAttributeMaxDynamicSharedMemorySize, SMEM_MUSIG);
        attr_set = true;
    }

    // rowsums (all 2944 rows in one launch)
    rowsum_all<<<(2944*32 + 255)/256, 256>>>(ra, Sp);

    // mu / sigma second-layer raw sums
    {
        dim3 grid(BNT/128, 2);
        musig_k<<<grid, 256, SMEM_MUSIG>>>(x, muW1, mub1, muW2, sgW1, sgb1, sgW2, ms);
    }
    softplus_k<<<(BNT*4 + 255)/256, 256>>>(mub2, sgb2);

    // wg (512 CTAs) + 4 fitters (512 CTAs) in one launch
    main_k<<<1024, 256, SMEM_MAIN>>>(eps, a);

    // final mixture + transpose
    {
        dim3 grid(Fc/FCHUNK, Bc);
        final_kernel<<<grid, 128>>>(out, fb2[0], fb2[1], fb2[2], fb2[3]);
    }
}

// round 12
// speedup vs baseline: 2.9074x; 1.1001x over previous
#include <cuda_runtime.h>
#include <cuda_bf16.h>
#include <math.h>
#include <stdint.h>

#define Tc   336
#define BNT  16384
#define Fc   720
#define Nch  128
#define Bc   128
#define KC   48          // k-cols per smem stage
#define NSTG 7           // 336/48
#define RSTR 112         // smem row stride bytes (48 bf16 = 96B + 16 pad; 112/16=7 coprime 8)
#define NTHR 512

// ---------------- scratch globals ----------------
__device__ float g_ms[BNT*8];
__device__ float g_spmu[BNT*4];
__device__ float g_spsg[BNT*4];
__device__ float g_w[BNT*4];
__device__ float g_coef[BNT*8];
__device__ float g_S[64 + 4*Fc];

__device__ __forceinline__ float softplus_f(float x){
    return fmaxf(x,0.f) + log1pf(expf(-fabsf(x)));
}
__device__ __forceinline__ uint32_t su32(const void* p){
    uint32_t a;
    asm("{ .reg .u64 t; cvta.to.shared.u64 t, %1; cvt.u32.u64 %0, t; }" : "=r"(a) : "l"(p));
    return a;
}

#define LDSM4(r, a) asm volatile( \
    "ldmatrix.sync.aligned.m8n8.x4.shared.b16 {%0,%1,%2,%3}, [%4];" \
    : "=r"((r)[0]), "=r"((r)[1]), "=r"((r)[2]), "=r"((r)[3]) : "r"(a))
#define MMA(c, a, b) asm volatile( \
    "mma.sync.aligned.m16n8k16.row.col.f32.bf16.bf16.f32 " \
    "{%0,%1,%2,%3}, {%4,%5,%6,%7}, {%8,%9}, {%0,%1,%2,%3};" \
    : "+f"((c)[0]), "+f"((c)[1]), "+f"((c)[2]), "+f"((c)[3]) \
    : "r"((a)[0]), "r"((a)[1]), "r"((a)[2]), "r"((a)[3]), "r"((b)[0]), "r"((b)[1]))

__device__ __forceinline__ void cvt_split(float4 v, uint2& h, uint2& lo){
    __nv_bfloat162 h01 = __floats2bfloat162_rn(v.x, v.y);
    __nv_bfloat162 h23 = __floats2bfloat162_rn(v.z, v.w);
    float2 f01 = __bfloat1622float2(h01), f23 = __bfloat1622float2(h23);
    __nv_bfloat162 l01 = __floats2bfloat162_rn(v.x - f01.x, v.y - f01.y);
    __nv_bfloat162 l23 = __floats2bfloat162_rn(v.z - f23.x, v.w - f23.y);
    h  = make_uint2(*(uint32_t*)&h01, *(uint32_t*)&h23);
    lo = make_uint2(*(uint32_t*)&l01, *(uint32_t*)&l23);
}

// =====================================================================
// 512-thread (16-warp, 4x4 grid) double-buffered split-bf16 mma.sync GEMM
// with fused reduce epilogue.
//   acc[m,n] = A[m,:].W1[n,:]  (K=336)
//   h = relu(b1[n] + smu[m]*S[n] + ssg[m]*acc)
//   WMODE 0: out[m*ostride+ooff+d] = sum_n h*W2[d,n]
//   WMODE 1: logits -> softmax over groups of 4 rows -> out (g_w)
// =====================================================================
template<int NTILE, int RT, int WMODE>
__device__ __forceinline__ void gemm_core(
    const float* __restrict__ A, int lda,
    const float* __restrict__ W1, int Ncols, int n_nt,
    const float* __restrict__ b1, const float* __restrict__ S,
    const float* __restrict__ spmu, const float* __restrict__ spsg,
    int sp_mul, int sp_add,
    const float* __restrict__ W2, int R,
    float* __restrict__ outp, int ostride, int ooff,
    int m0, char* smem)
{
    constexpr int AHALF = 128*RSTR;            // bytes per A half-tile
    constexpr int BHALF = NTILE*RSTR;
    constexpr int BUFSZ = 2*AHALF + 2*BHALF;
    constexpr int NB4   = (NTILE*12 + NTHR-1)/NTHR;  // B float4 per thread per stage
    constexpr bool BGUARD = (NTILE*12 % NTHR) != 0;
    constexpr int NJ    = NTILE/32;            // n8 tiles per warp (4x4 grid)
    constexpr int NPW   = NTILE/4;             // N cols per warp

    const int tid = threadIdx.x;
    const int wid = tid >> 5, lane = tid & 31;
    const int g = lane >> 2, l = lane & 3;
    const int wm = wid >> 2, wn = wid & 3;     // 4x4 warp grid; warp tile 32 x NPW
    const uint32_t sb = su32(smem);
    float* stg = (float*)(smem + 2*BUFSZ);
    float* red = (float*)(smem + 2*BUFSZ + (2+RT)*NTILE*4);

    if (tid < 128) ((float4*)red)[tid] = make_float4(0.f,0.f,0.f,0.f);

    float part[4][RT];
    #pragma unroll
    for (int s = 0; s < 4; s++)
        #pragma unroll
        for (int d = 0; d < RT; d++) part[s][d] = 0.f;

    float4 pa[3], pb[NB4];

    auto ldgA = [&](int kc){
        #pragma unroll
        for (int it = 0; it < 3; it++){
            int q = tid + it*NTHR; int r = q/12, cq = q - r*12;
            pa[it] = *(const float4*)(A + (long)(m0 + r)*lda + kc*KC + cq*4);
        }
    };
    auto ldgB = [&](int nt, int kc){
        #pragma unroll
        for (int it = 0; it < NB4; it++){
            int q = tid + it*NTHR;
            if (!BGUARD || q < NTILE*12){
                int n = q/12, cq = q - n*12;
                int gn = nt*NTILE + n;
                pb[it] = (gn < Ncols) ? *(const float4*)(W1 + (long)gn*Tc + kc*KC + cq*4)
                                      : make_float4(0.f,0.f,0.f,0.f);
            }
        }
    };
    auto sts = [&](int buf){
        char* bb = smem + buf*BUFSZ;
        #pragma unroll
        for (int it = 0; it < 3; it++){
            int q = tid + it*NTHR; int r = q/12, cq = q - r*12;
            uint2 h, lo; cvt_split(pa[it], h, lo);
            *(uint2*)(bb + r*RSTR + cq*8) = h;
            *(uint2*)(bb + AHALF + r*RSTR + cq*8) = lo;
        }
        #pragma unroll
        for (int it = 0; it < NB4; it++){
            int q = tid + it*NTHR;
            if (!BGUARD || q < NTILE*12){
                int n = q/12, cq = q - n*12;
                uint2 h, lo; cvt_split(pb[it], h, lo);
                *(uint2*)(bb + 2*AHALF + n*RSTR + cq*8) = h;
                *(uint2*)(bb + 2*AHALF + BHALF + n*RSTR + cq*8) = lo;
            }
        }
    };

    for (int nt = 0; nt < n_nt; nt++){
        __syncthreads();   // stg reuse + buf0 reuse safety
        // staging: b1 / S / W2 rows for this n-tile
        for (int idx = tid; idx < NTILE*(2+RT); idx += NTHR){
            int n = idx % NTILE, row = idx / NTILE;
            int gn = nt*NTILE + n;
            float v = 0.f;
            if (gn < Ncols){
                if (row == 0)           v = b1[gn];
                else if (row == 1)      v = (S != nullptr) ? S[gn] : 0.f;
                else if (row - 2 < R)   v = W2[(row-2)*Ncols + gn];
            }
            stg[row*NTILE + n] = v;
        }

        float acc[2][NJ][4];
        #pragma unroll
        for (int i = 0; i < 2; i++)
            #pragma unroll
            for (int j = 0; j < NJ; j++)
                #pragma unroll
                for (int e = 0; e < 4; e++) acc[i][j][e] = 0.f;

        ldgA(0); ldgB(nt, 0);
        sts(0);
        __syncthreads();

        // one MMA k-step (k16) over the given buffer
        auto mma_step = [&](uint32_t base, int ks){
            uint32_t ah[2][4], al[2][4];
            #pragma unroll
            for (int i = 0; i < 2; i++){
                int row = wm*32 + i*16 + (lane & 15);
                uint32_t ad = base + row*RSTR + ks*32 + ((lane>>4)<<4);
                LDSM4(ah[i], ad);
                LDSM4(al[i], ad + AHALF);
            }
            uint32_t bh[NJ][2], bl[NJ][2];
            #pragma unroll
            for (int p = 0; p < NJ/2; p++){
                int rowb = wn*NPW + p*16 + ((lane>>4)<<3) + (lane & 7);
                uint32_t ad = base + 2*AHALF + rowb*RSTR + ks*32 + (((lane>>3)&1)<<4);
                uint32_t t[4];
                LDSM4(t, ad);
                bh[2*p][0]=t[0]; bh[2*p][1]=t[1]; bh[2*p+1][0]=t[2]; bh[2*p+1][1]=t[3];
                LDSM4(t, ad + BHALF);
                bl[2*p][0]=t[0]; bl[2*p][1]=t[1]; bl[2*p+1][0]=t[2]; bl[2*p+1][1]=t[3];
            }
            #pragma unroll
            for (int i = 0; i < 2; i++)
                #pragma unroll
                for (int j = 0; j < NJ; j++){
                    MMA(acc[i][j], ah[i], bh[j]);
                    MMA(acc[i][j], ah[i], bl[j]);
                    MMA(acc[i][j], al[i], bh[j]);
                }
        };

        for (int kc = 0; kc < NSTG; kc++){
            const uint32_t base = sb + (kc & 1)*BUFSZ;
            const bool more = (kc + 1 < NSTG);
            if (more){ ldgA(kc+1); ldgB(nt, kc+1); }
            mma_step(base, 0);
            mma_step(base, 1);
            if (more) sts((kc+1) & 1);   // STS next buffer between MMA k-steps
            mma_step(base, 2);
            __syncthreads();
        }

        // ---- epilogue: relu + affine + partial n-reduction ----
        float smu4[4], ssg4[4];
        #pragma unroll
        for (int s = 0; s < 4; s++){
            if (spmu != nullptr){
                int row = m0 + wm*32 + (s>>1)*16 + g + (s&1)*8;
                smu4[s] = spmu[row*sp_mul + sp_add];
                ssg4[s] = spsg[row*sp_mul + sp_add];
            } else { smu4[s] = 0.f; ssg4[s] = 1.f; }
        }
        #pragma unroll
        for (int i = 0; i < 2; i++)
            #pragma unroll
            for (int j = 0; j < NJ; j++)
                #pragma unroll
                for (int e = 0; e < 4; e++){
                    int nl = wn*NPW + j*8 + 2*l + (e&1);
                    int s  = i*2 + (e>>1);
                    float hv = fmaxf(stg[nl] + smu4[s]*stg[NTILE+nl] + ssg4[s]*acc[i][j][e], 0.f);
                    #pragma unroll
                    for (int d = 0; d < RT; d++)
                        part[s][d] += stg[(2+d)*NTILE + nl] * hv;
                }
    }

    // cross-lane (l) reduce, then cross-warp via smem atomics
    #pragma unroll
    for (int s = 0; s < 4; s++)
        #pragma unroll
        for (int d = 0; d < RT; d++){
            float v = part[s][d];
            v += __shfl_xor_sync(0xffffffffu, v, 1);
            v += __shfl_xor_sync(0xffffffffu, v, 2);
            part[s][d] = v;
        }
    if (l == 0){
        #pragma unroll
        for (int s = 0; s < 4; s++){
            int rl = wm*32 + (s>>1)*16 + g + (s&1)*8;
            #pragma unroll
            for (int d = 0; d < RT; d++)
                if (d < R) atomicAdd(&red[rl*4 + d], part[s][d]);
        }
    }
    __syncthreads();
    if (WMODE == 0){
        if (tid < 128)
            for (int d = 0; d < R; d++)
                outp[(long)(m0 + tid)*ostride + ooff + d] = red[tid*4 + d];
    } else {
        if (tid < 32){
            float lg0 = red[(tid*4+0)*4], lg1 = red[(tid*4+1)*4];
            float lg2 = red[(tid*4+2)*4], lg3 = red[(tid*4+3)*4];
            float m = fmaxf(fmaxf(lg0,lg1), fmaxf(lg2,lg3));
            float e0 = expf(lg0-m), e1 = expf(lg1-m), e2 = expf(lg2-m), e3 = expf(lg3-m);
            float inv = 1.f/(e0+e1+e2+e3);
            outp[m0 + tid*4 + 0] = e0*inv; outp[m0 + tid*4 + 1] = e1*inv;
            outp[m0 + tid*4 + 2] = e2*inv; outp[m0 + tid*4 + 3] = e3*inv;
        }
    }
}

// ---------------- kernels ----------------
struct MainArgs {
    const float *wgW1, *wgb1, *wgW2, *Sp, *spm, *sps;
    const float *fW1[4], *fb1[4], *fW2[4];
    float *gw, *cf;
};

__global__ __launch_bounds__(NTHR,1) void main_k(const float* __restrict__ eps, MainArgs a)
{
    extern __shared__ char smem[];
    int bid = blockIdx.x;
    if (bid < 512){   // fitters first: heavy CTAs start in wave 1
        int i  = bid >> 7;
        int m0 = (bid & 127)*128;
        int R   = (i == 2) ? 3 : ((i == 1) ? 2 : 1);
        int off = (i == 0) ? 0 : (i == 1) ? 1 : (i == 2) ? 3 : 6;
        gemm_core<128,3,0>(eps + i*Tc, 4*Tc, a.fW1[i], Fc, 6, a.fb1[i],
                           a.Sp + 64 + i*Fc, a.spm, a.sps, 4, i,
                           a.fW2[i], R, a.cf, 8, off, m0, smem);
    } else {
        int m0 = (bid - 512)*128;
        gemm_core<64,1,1>(eps, Tc, a.wgW1, 64, 1, a.wgb1, a.Sp,
                          a.spm, a.sps, 1, 0, a.wgW2, 1,
                          a.gw, 1, 0, m0, smem);
    }
}

__global__ __launch_bounds__(NTHR,1) void musig_k(
    const float* __restrict__ x,
    const float* muW1, const float* mub1, const float* muW2,
    const float* sgW1, const float* sgb1, const float* sgW2, float* ms)
{
    extern __shared__ char smem[];
    if (blockIdx.y == 0)
        gemm_core<64,4,0>(x, Tc, muW1, 64, 1, mub1, nullptr, nullptr, nullptr, 0, 0,
                          muW2, 4, ms, 8, 0, blockIdx.x*128, smem);
    else
        gemm_core<64,4,0>(x, Tc, sgW1, 64, 1, sgb1, nullptr, nullptr, nullptr, 0, 0,
                          sgW2, 4, ms, 8, 4, blockIdx.x*128, smem);
}

struct RowArgs { const float *wg, *f[4]; };
__global__ void rowsum_all(RowArgs ra, float* __restrict__ S)
{
    int r = (blockIdx.x * blockDim.x + threadIdx.x) >> 5;
    int lane = threadIdx.x & 31;
    if (r >= 64 + 4*Fc) return;
    const float* row;
    if (r < 64) row = ra.wg + (long)r*Tc;
    else { int i = (r-64)/Fc, rr = (r-64) - i*Fc; row = ra.f[i] + (long)rr*Tc; }
    float s = 0.f;
    for (int j = lane; j < Tc; j += 32) s += row[j];
    #pragma unroll
    for (int o = 16; o; o >>= 1) s += __shfl_xor_sync(0xffffffffu, s, o);
    if (lane == 0) S[r] = s;
}

__global__ void softplus_k(const float* __restrict__ mub2, const float* __restrict__ sgb2){
    int i = blockIdx.x*256 + threadIdx.x;
    if (i >= BNT*4) return;
    int row = i >> 2, k = i & 3;
    g_spmu[i] = softplus_f(g_ms[row*8 + k]     + mub2[k]);
    g_spsg[i] = softplus_f(g_ms[row*8 + 4 + k] + sgb2[k]);
}

#define FCHUNK 48
__global__ void final_kernel(float* __restrict__ out,
                             const float* __restrict__ b2_0, const float* __restrict__ b2_1,
                             const float* __restrict__ b2_2, const float* __restrict__ b2_3){
    int b  = blockIdx.y;
    int f0 = blockIdx.x * FCHUNK;
    int n  = threadIdx.x;
    int bn = b * Nch + n;
    float w0 = g_w[bn*4+0], w1 = g_w[bn*4+1], w2 = g_w[bn*4+2], w3 = g_w[bn*4+3];
    float c0 = g_coef[bn*8+0] + b2_0[0];
    float c1 = g_coef[bn*8+1] + b2_1[0], c2 = g_coef[bn*8+2] + b2_1[1];
    float c3 = g_coef[bn*8+3] + b2_2[0], c4 = g_coef[bn*8+4] + b2_2[1], c5 = g_coef[bn*8+5] + b2_2[2];
    float c6 = g_coef[bn*8+6] + b2_3[0];
    #pragma unroll 4
    for (int fi = 0; fi < FCHUNK; fi++) {
        int f = f0 + fi;
        float tt = (float)f * (1.f/719.f);
        float t2 = tt*tt, t3 = t2*tt;
        float p0 = c0 + 0.5f*tt;
        float p1 = c1 + c2*tt + 0.5f*t2;
        float p2 = c3 + c4*tt + c5*t2 + 0.5f*t3;
        float p3 = c6 - 0.5f*tt;
        out[((long)b*Fc + f)*Nch + n] = w0*p0 + w1*p1 + w2*p2 + w3*p3;
    }
}

// ---------------- launch ----------------
extern "C" void kernel_launch(void* const* d_in, const int* in_sizes, int n_in,
                              void* d_out, int out_size)
{
    const float* x     = (const float*)d_in[0];
    const float* eps   = (const float*)d_in[1];
    const float* muW1  = (const float*)d_in[2];
    const float* mub1  = (const float*)d_in[3];
    const float* muW2  = (const float*)d_in[4];
    const float* mub2  = (const float*)d_in[5];
    const float* sgW1  = (const float*)d_in[6];
    const float* sgb1  = (const float*)d_in[7];
    const float* sgW2  = (const float*)d_in[8];
    const float* sgb2  = (const float*)d_in[9];
    const float* wgW1  = (const float*)d_in[10];
    const float* wgb1  = (const float*)d_in[11];
    const float* wgW2  = (const float*)d_in[12];
    // d_in[13] = wgb2 (cancels in softmax)
    const float* fb2[4] = {(const float*)d_in[17], (const float*)d_in[21],
                           (const float*)d_in[25], (const float*)d_in[29]};
    float* out = (float*)d_out;

    float* ms;  cudaGetSymbolAddress((void**)&ms,  g_ms);
    float* spm; cudaGetSymbolAddress((void**)&spm, g_spmu);
    float* sps; cudaGetSymbolAddress((void**)&sps, g_spsg);
    float* gw;  cudaGetSymbolAddress((void**)&gw,  g_w);
    float* cf;  cudaGetSymbolAddress((void**)&cf,  g_coef);
    float* Sp;  cudaGetSymbolAddress((void**)&Sp,  g_S);

    MainArgs a;
    a.wgW1 = wgW1; a.wgb1 = wgb1; a.wgW2 = wgW2;
    a.Sp = Sp; a.spm = spm; a.sps = sps; a.gw = gw; a.cf = cf;
    a.fW1[0] = (const float*)d_in[14]; a.fb1[0] = (const float*)d_in[15]; a.fW2[0] = (const float*)d_in[16];
    a.fW1[1] = (const float*)d_in[18]; a.fb1[1] = (const float*)d_in[19]; a.fW2[1] = (const float*)d_in[20];
    a.fW1[2] = (const float*)d_in[22]; a.fb1[2] = (const float*)d_in[23]; a.fW2[2] = (const float*)d_in[24];
    a.fW1[3] = (const float*)d_in[26]; a.fb1[3] = (const float*)d_in[27]; a.fW2[3] = (const float*)d_in[28];

    RowArgs ra;
    ra.wg = wgW1;
    for (int i = 0; i < 4; i++) ra.f[i] = a.fW1[i];

    // smem: NT=128/RT=3: 2*(2*14336+2*128*112) + 5*128*4 + 2048 = 119296
    //       NT=64 /RT=4: 2*(2*14336+2* 64*112) + 6* 64*4 + 2048 = 89600
    const int SMEM_MAIN  = 119296;
    const int SMEM_MUSIG = 89600;
    static bool attr_set = false;
    if (!attr_set){
        cudaFuncSetAttribute(main_k,  cudaFuncAttributeMaxDynamicSharedMemorySize, SMEM_MAIN);
        cudaFuncSetAttribute(musig_k, cudaFuncAttributeMaxDynamicSharedMemorySize, SMEM_MUSIG);
        attr_set = true;
    }

    // rowsums (all 2944 rows in one launch)
    rowsum_all<<<(2944*32 + 255)/256, 256>>>(ra, Sp);

    // mu / sigma second-layer raw sums
    {
        dim3 grid(BNT/128, 2);
        musig_k<<<grid, NTHR, SMEM_MUSIG>>>(x, muW1, mub1, muW2, sgW1, sgb1, sgW2, ms);
    }
    softplus_k<<<(BNT*4 + 255)/256, 256>>>(mub2, sgb2);

    // fitters (512 CTAs, first) + wg (512 CTAs) in one launch
    main_k<<<1024, NTHR, SMEM_MAIN>>>(eps, a);

    // final mixture + transpose
    {
        dim3 grid(Fc/FCHUNK, Bc);
        final_kernel<<<grid, 128>>>(out, fb2[0], fb2[1], fb2[2], fb2[3]);
    }
}